// round 15
// baseline (speedup 1.0000x reference)
#include <cuda_runtime.h>
#include <cstdint>

#define NB 4
#define NL 512
#define ND 128
#define L2E 1.4426950408889634f

// Scratch (static device arrays)
__device__ float g_a [NB*NL*ND];     // 1 MB
__device__ float g_bm[NB*NL*ND];     // 1 MB
__device__ float g_sc[NB*NL*NL];     // 4 MB: exp(score), unnormalized
__device__ float g_ps[NB*16*NL];     // per (b, i-tile, j) partial column sums

__device__ __forceinline__ float tanh_fast(float x) {
    float y; asm("tanh.approx.f32 %0, %1;" : "=f"(y) : "f"(x)); return y;
}
__device__ __forceinline__ float ex2_fast(float x) {
    float y; asm("ex2.approx.ftz.f32 %0, %1;" : "=f"(y) : "f"(x)); return y;
}
__device__ __forceinline__ float rcp_fast(float x) {
    float y; asm("rcp.approx.ftz.f32 %0, %1;" : "=f"(y) : "f"(x)); return y;
}
__device__ __forceinline__ void cp_async16(unsigned int dst, const void* src) {
    asm volatile("cp.async.cg.shared.global [%0], [%1], 16;\n" :: "r"(dst), "l"(src));
}
__device__ __forceinline__ unsigned int smem_u32(const void* p) {
    unsigned int a;
    asm("{ .reg .u64 t; cvta.to.shared.u64 t, %1; cvt.u32.u64 %0, t; }" : "=r"(a) : "l"(p));
    return a;
}

// ---------------------------------------------------------------------------
// Kernel A v3: projections, fragment geometry + swizzled W staging.
//   e < 128 : a [row][e] = sum_d hs[row][d] * W[e, d]
//   e >= 128: bm[row][e-128] = sum_d hs[row][d] * W[e-128, 128+d]
// Block: 32 rows x 32 fused outputs, 128 threads, grid (64, 8) = 512 blocks.
// Warp = 32 rows x 8 outputs; thread = 2 rows x float4 of outputs.
// W_s column swizzle: c' = (c + ((d&24)>>1)) & 31  -> conflict-free STS
// (banks (4d + c') mod 32 distinct across the 32 consecutive d per warp)
// while float4 groups stay contiguous for the main-loop LDS.128.
// ---------------------------------------------------------------------------
__global__ void __launch_bounds__(128, 6)
proj_kernel(const float* __restrict__ hs, const float* __restrict__ W) {
    __shared__ float hs_t[128 * 33];                  // 16.9 KB [d][row]
    __shared__ __align__(16) float W_s[128 * 36];     // 18.4 KB [d][swizzled c]
    const int rowbase = blockIdx.x * 32;
    const int e0      = blockIdx.y * 32;              // 0..224, step 32
    const int tid  = threadIdx.x;
    const int wid  = tid >> 5;
    const int lane = tid & 31;
    const int r = lane >> 1;          // row-pair index 0..15
    const int c = lane & 1;
    const int efrag = wid * 8 + c * 4;

    // Uniform per block: which half of the fused outputs.
    const float* Wb  = (e0 < 128) ? (W + e0 * 256) : (W + (e0 - 128) * 256 + 128);
    float* outb      = (e0 < 128) ? g_a : g_bm;
    const int eoff   = (e0 < 128) ? e0 : (e0 - 128);

    // Stage hs transposed (coalesced LDG, stride-33 STS conflict-free).
    {
        const int dl  = tid & 31;
        const int rw4 = tid >> 5;               // 0..3
#pragma unroll 4
        for (int it = 0; it < 8; it++) {
            int row = rw4 * 8 + it;             // 0..31
#pragma unroll
            for (int dc = 0; dc < 4; dc++) {
                int d = dc * 32 + dl;
                hs_t[d * 33 + row] = hs[(rowbase + row) * 128 + d];
            }
        }
    }
    // Stage W (coalesced along d, swizzled STS -> conflict-free).
#pragma unroll 4
    for (int it = 0; it < 32; it++) {
        int k = tid + 128 * it;                 // k = cc*128 + d
        int cc = k >> 7, d = k & 127;
        int csw = (cc + ((d & 24) >> 1)) & 31;
        W_s[d * 36 + csw] = Wb[cc * 256 + d];
    }
    __syncthreads();

    float4 acc0 = make_float4(0.f, 0.f, 0.f, 0.f);
    float4 acc1 = make_float4(0.f, 0.f, 0.f, 0.f);
#pragma unroll 4
    for (int d = 0; d < 128; d++) {
        float h0 = hs_t[d * 33 + r * 2];
        float h1 = hs_t[d * 33 + r * 2 + 1];
        int esw = (efrag + ((d & 24) >> 1)) & 31;
        float4 wf = *(const float4*)&W_s[d * 36 + esw];     // broadcast
        acc0.x += h0 * wf.x;  acc0.y += h0 * wf.y;
        acc0.z += h0 * wf.z;  acc0.w += h0 * wf.w;
        acc1.x += h1 * wf.x;  acc1.y += h1 * wf.y;
        acc1.z += h1 * wf.z;  acc1.w += h1 * wf.w;
    }

    const int row0 = rowbase + r * 2;
    *(float4*)&outb[ row0      * 128 + eoff + efrag] = acc0;
    *(float4*)&outb[(row0 + 1) * 128 + eoff + efrag] = acc1;
}

// ---------------------------------------------------------------------------
// Kernel B (MUFU-bound): writes E[b,i,j] = exp( sum_d v[d]*tanh(a+bm) )
// (no max subtraction: |score| <= sum(v) ~ 64, exp fits fp32), plus a
// per-block partial column sum over its 32 i-rows -> g_ps[b][i_tile][j].
// grid (16,16,4), 256 threads, 2x2 micro-tile, float4 smem (pitch 33 vec4)
// ---------------------------------------------------------------------------
__global__ void score_kernel(const float* __restrict__ v) {
    __shared__ float4 a_s[32 * 33];     // 16.9 KB, row pitch 33 float4
    __shared__ float4 b_s[32 * 33];
    __shared__ float4 v_s[32];
    __shared__ float  cred[16][32];     // 2 KB column-sum reduction
    const int bi = blockIdx.z;
    const int i0 = blockIdx.x * 32, j0 = blockIdx.y * 32;
    const int tid = threadIdx.x;

    const float4* ga4 = (const float4*)g_a;
    const float4* gb4 = (const float4*)g_bm;
    for (int k = tid; k < 32 * 32; k += 256) {
        int r = k >> 5, q = k & 31;
        a_s[r * 33 + q] = ga4[(bi * NL + i0 + r) * 32 + q];
        b_s[r * 33 + q] = gb4[(bi * NL + j0 + r) * 32 + q];
    }
    if (tid < 32) v_s[tid] = ((const float4*)v)[tid];
    __syncthreads();

    const int ty = tid >> 4, tx = tid & 15;
    float acc00 = 0.f, acc01 = 0.f, acc10 = 0.f, acc11 = 0.f;
#pragma unroll 8
    for (int q = 0; q < 32; q++) {
        float4 vq = v_s[q];
        float4 a0 = a_s[ ty       * 33 + q];
        float4 a1 = a_s[(ty + 16) * 33 + q];
        float4 b0 = b_s[ tx       * 33 + q];
        float4 b1 = b_s[(tx + 16) * 33 + q];
        acc00 += vq.x * tanh_fast(a0.x + b0.x);
        acc00 += vq.y * tanh_fast(a0.y + b0.y);
        acc00 += vq.z * tanh_fast(a0.z + b0.z);
        acc00 += vq.w * tanh_fast(a0.w + b0.w);
        acc01 += vq.x * tanh_fast(a0.x + b1.x);
        acc01 += vq.y * tanh_fast(a0.y + b1.y);
        acc01 += vq.z * tanh_fast(a0.z + b1.z);
        acc01 += vq.w * tanh_fast(a0.w + b1.w);
        acc10 += vq.x * tanh_fast(a1.x + b0.x);
        acc10 += vq.y * tanh_fast(a1.y + b0.y);
        acc10 += vq.z * tanh_fast(a1.z + b0.z);
        acc10 += vq.w * tanh_fast(a1.w + b0.w);
        acc11 += vq.x * tanh_fast(a1.x + b1.x);
        acc11 += vq.y * tanh_fast(a1.y + b1.y);
        acc11 += vq.z * tanh_fast(a1.z + b1.z);
        acc11 += vq.w * tanh_fast(a1.w + b1.w);
    }
    float e00 = ex2_fast(acc00 * L2E);
    float e01 = ex2_fast(acc01 * L2E);
    float e10 = ex2_fast(acc10 * L2E);
    float e11 = ex2_fast(acc11 * L2E);

    float* sp = g_sc + (size_t)bi * NL * NL;
    sp[(i0 + ty     ) * NL + j0 + tx     ] = e00;
    sp[(i0 + ty     ) * NL + j0 + tx + 16] = e01;
    sp[(i0 + ty + 16) * NL + j0 + tx     ] = e10;
    sp[(i0 + ty + 16) * NL + j0 + tx + 16] = e11;

    // partial column sums over this block's 32 i-rows (fixed order -> determ.)
    cred[ty][tx]      = e00 + e10;
    cred[ty][tx + 16] = e01 + e11;
    __syncthreads();
    if (tid < 32) {
        float s = 0.f;
#pragma unroll
        for (int r2 = 0; r2 < 16; r2++) s += cred[r2][tid];
        g_ps[(bi * 16 + blockIdx.x) * NL + j0 + tid] = s;
    }
}

// ---------------------------------------------------------------------------
// Kernel C v9: out[b,i,d] = sum_j (E[b,i,j] * inv[b,j]) * hs[b,j,d]
// 64-j chunks (8 chunks -> half the syncs of v8). Preamble folds the 16
// per-tile partial sums, rcp -> inv_sh; w staging multiplies by inv_sh.
// 128-thread CTAs, 32 i x 32 d, grid (16,4,4)=256. smem 35.4 KB.
// ---------------------------------------------------------------------------
__global__ void __launch_bounds__(128, 4)
out_kernel(const float* __restrict__ hs, float* __restrict__ out) {
    __shared__ float inv_sh[NL];                      // 2 KB
    __shared__ float w_s[2][64 * 34];                 // 17.4 KB [j][row] pitch 34
    __shared__ __align__(16) float h_s[2][64 * 32];   // 16 KB   [j][d]
    const int i0 = blockIdx.x * 32;
    const int bi = blockIdx.y;
    const int d0 = blockIdx.z * 32;
    const int tid  = threadIdx.x;
    const int wid  = tid >> 5;        // 0..3
    const int lane = tid & 31;
    const int r = lane >> 1;          // row-pair index 0..15
    const int c = lane & 1;           // float4 column 0..1
    const int dfrag = wid * 8 + c * 4;

    const float* scb = g_sc + (size_t)bi * NL * NL;

    // ---- preamble: column sums -> inverses ----
    for (int j = tid; j < NL; j += 128) {
        float s = 0.f;
#pragma unroll
        for (int it = 0; it < 16; it++)
            s += g_ps[(bi * 16 + it) * NL + j];
        inv_sh[j] = rcp_fast(s);
    }

    // ---- prologue: chunk 0 (j 0..63) ----
    float rw[16];
#pragma unroll
    for (int s = 0; s < 16; s++) {
        int k = tid + 128 * s;                 // k = row*64 + jl (coalesced jl)
        rw[s] = scb[(i0 + (k >> 6)) * NL + (k & 63)];
    }
#pragma unroll
    for (int s = 0; s < 4; s++) {
        int k = tid + 128 * s;                 // k = j*8 + seg
        int j = k >> 3, seg = k & 7;
        cp_async16(smem_u32(&h_s[0][j * 32 + seg * 4]),
                   &hs[(bi * NL + j) * ND + d0 + seg * 4]);
    }
    asm volatile("cp.async.commit_group;\n" ::: "memory");
    __syncthreads();                           // inv_sh visible
#pragma unroll
    for (int s = 0; s < 16; s++) {
        int k = tid + 128 * s;
        int row = k >> 6, jl = k & 63;
        w_s[0][jl * 34 + row] = rw[s] * inv_sh[jl];
    }
    asm volatile("cp.async.wait_group 0;\n" ::: "memory");
    __syncthreads();

    float4 acc0 = make_float4(0.f, 0.f, 0.f, 0.f);
    float4 acc1 = make_float4(0.f, 0.f, 0.f, 0.f);

    int p = 0;
    for (int ch = 0; ch < 8; ch++) {
        const int jn = (ch + 1) * 64;
        if (ch < 7) {
            // prefetch next w tile (regs) + next h tile (cp.async, other buffer)
#pragma unroll
            for (int s = 0; s < 16; s++) {
                int k = tid + 128 * s;
                rw[s] = scb[(i0 + (k >> 6)) * NL + jn + (k & 63)];
            }
#pragma unroll
            for (int s = 0; s < 4; s++) {
                int k = tid + 128 * s;
                int j = k >> 3, seg = k & 7;
                cp_async16(smem_u32(&h_s[p ^ 1][j * 32 + seg * 4]),
                           &hs[(bi * NL + jn + j) * ND + d0 + seg * 4]);
            }
            asm volatile("cp.async.commit_group;\n" ::: "memory");
        }

        const float* wp = w_s[p];
        const float* hp = h_s[p];
#pragma unroll 8
        for (int j = 0; j < 64; j++) {
            float2 wf = *(const float2*)&wp[j * 34 + r * 2];   // 128B/warp
            float4 hf = *(const float4*)&hp[j * 32 + dfrag];   // 32B/warp
            acc0.x += wf.x * hf.x;  acc0.y += wf.x * hf.y;
            acc0.z += wf.x * hf.z;  acc0.w += wf.x * hf.w;
            acc1.x += wf.y * hf.x;  acc1.y += wf.y * hf.y;
            acc1.z += wf.y * hf.z;  acc1.w += wf.y * hf.w;
        }

        if (ch < 7) {
#pragma unroll
            for (int s = 0; s < 16; s++) {
                int k = tid + 128 * s;
                int row = k >> 6, jl = k & 63;
                w_s[p ^ 1][jl * 34 + row] = rw[s] * inv_sh[jn + jl];
            }
            asm volatile("cp.async.wait_group 0;\n" ::: "memory");
            __syncthreads();
        }
        p ^= 1;
    }

    float* ob = out + ((size_t)bi * NL + i0 + r * 2) * ND + d0 + dfrag;
    *(float4*)&ob[0]  = acc0;
    *(float4*)&ob[ND] = acc1;
}

// ---------------------------------------------------------------------------
extern "C" void kernel_launch(void* const* d_in, const int* in_sizes, int n_in,
                              void* d_out, int out_size) {
    const float* hs = (const float*)d_in[0];   // (4,512,128)
    const float* W  = (const float*)d_in[1];   // (128,256)
    const float* v  = (const float*)d_in[2];   // (128,)
    float* out = (float*)d_out;                // (4,512,128)

    proj_kernel <<<dim3(64, 8),     128>>>(hs, W);
    score_kernel<<<dim3(16, 16, 4), 256>>>(v);
    out_kernel  <<<dim3(16, 4, 4),  128>>>(hs, out);
}

// round 16
// speedup vs baseline: 1.0350x; 1.0350x over previous
#include <cuda_runtime.h>
#include <cstdint>

#define NB 4
#define NL 512
#define ND 128
#define L2E 1.4426950408889634f

// Scratch (static device arrays)
__device__ float g_a [NB*NL*ND];     // 1 MB
__device__ float g_bm[NB*NL*ND];     // 1 MB
__device__ float g_sc[NB*NL*NL];     // 4 MB: exp(score), unnormalized
__device__ float g_ps[NB*16*NL];     // per (b, i-tile, j) partial column sums

__device__ __forceinline__ float tanh_fast(float x) {
    float y; asm("tanh.approx.f32 %0, %1;" : "=f"(y) : "f"(x)); return y;
}
__device__ __forceinline__ float ex2_fast(float x) {
    float y; asm("ex2.approx.ftz.f32 %0, %1;" : "=f"(y) : "f"(x)); return y;
}
__device__ __forceinline__ float rcp_fast(float x) {
    float y; asm("rcp.approx.ftz.f32 %0, %1;" : "=f"(y) : "f"(x)); return y;
}
__device__ __forceinline__ void cp_async16(unsigned int dst, const void* src) {
    asm volatile("cp.async.cg.shared.global [%0], [%1], 16;\n" :: "r"(dst), "l"(src));
}
__device__ __forceinline__ unsigned int smem_u32(const void* p) {
    unsigned int a;
    asm("{ .reg .u64 t; cvta.to.shared.u64 t, %1; cvt.u32.u64 %0, t; }" : "=r"(a) : "l"(p));
    return a;
}

// ---------------------------------------------------------------------------
// Kernel A v2b: projections, R13-v2 geometry (NO reg cap, NO inner swizzle;
// only the uniform half-selection hoisted out of staging).
//   e < 128 : a [row][e] = sum_d hs[row][d] * W[e, d]
//   e >= 128: bm[row][e-128] = sum_d hs[row][d] * W[e-128, 128+d]
// Block: 32 rows x 32 fused outputs, 128 threads, grid (64, 8) = 512 blocks.
// Warp = 32 rows x 8 outputs; thread = 2 rows x float4 of outputs.
// Per d: 2 LDS.32 row-frag (pitch 33) + 1 LDS.128 col-frag bcast (pitch 36)
//        + 8 FFMA. smem 35.3 KB.
// ---------------------------------------------------------------------------
__global__ void __launch_bounds__(128, 4)
proj_kernel(const float* __restrict__ hs, const float* __restrict__ W) {
    __shared__ float hs_t[128 * 33];                  // 16.9 KB [d][row]
    __shared__ __align__(16) float W_s[128 * 36];     // 18.4 KB [d][c]
    const int rowbase = blockIdx.x * 32;
    const int e0      = blockIdx.y * 32;              // 0..224, step 32
    const int tid  = threadIdx.x;
    const int wid  = tid >> 5;
    const int lane = tid & 31;
    const int r = lane >> 1;          // row-pair index 0..15
    const int c = lane & 1;
    const int efrag = wid * 8 + c * 4;

    // Uniform per block: which half of the fused outputs.
    const float* Wb  = (e0 < 128) ? (W + e0 * 256) : (W + (e0 - 128) * 256 + 128);
    float* outb      = (e0 < 128) ? g_a : g_bm;
    const int eoff   = (e0 < 128) ? e0 : (e0 - 128);

    // Stage hs transposed (coalesced LDG, stride-33 STS conflict-free).
    {
        const int dl  = tid & 31;
        const int rw4 = tid >> 5;               // 0..3
#pragma unroll
        for (int it = 0; it < 8; it++) {
            int row = rw4 + it * 4;             // 0..31
#pragma unroll
            for (int dc = 0; dc < 4; dc++) {
                int d = dc * 32 + dl;
                hs_t[d * 33 + row] = hs[(rowbase + row) * 128 + d];
            }
        }
    }
    // Stage W: coalesced along d; W_s[d][c] pitch 36 (unswizzled).
#pragma unroll
    for (int it = 0; it < 32; it++) {
        int k = tid + 128 * it;                 // k = cc*128 + d
        int cc = k >> 7, d = k & 127;
        W_s[d * 36 + cc] = Wb[cc * 256 + d];
    }
    __syncthreads();

    float4 acc0 = make_float4(0.f, 0.f, 0.f, 0.f);
    float4 acc1 = make_float4(0.f, 0.f, 0.f, 0.f);
#pragma unroll 4
    for (int d = 0; d < 128; d++) {
        float h0 = hs_t[d * 33 + r * 2];
        float h1 = hs_t[d * 33 + r * 2 + 1];
        float4 wf = *(const float4*)&W_s[d * 36 + efrag];   // broadcast
        acc0.x += h0 * wf.x;  acc0.y += h0 * wf.y;
        acc0.z += h0 * wf.z;  acc0.w += h0 * wf.w;
        acc1.x += h1 * wf.x;  acc1.y += h1 * wf.y;
        acc1.z += h1 * wf.z;  acc1.w += h1 * wf.w;
    }

    const int row0 = rowbase + r * 2;
    *(float4*)&outb[ row0      * 128 + eoff + efrag] = acc0;
    *(float4*)&outb[(row0 + 1) * 128 + eoff + efrag] = acc1;
}

// ---------------------------------------------------------------------------
// Kernel B (MUFU-bound): writes E[b,i,j] = exp( sum_d v[d]*tanh(a+bm) )
// (no max subtraction: |score| <= sum(v) ~ 64, exp fits fp32), plus a
// per-block partial column sum over its 32 i-rows -> g_ps[b][i_tile][j].
// grid (16,16,4), 256 threads, 2x2 micro-tile, float4 smem (pitch 33 vec4)
// ---------------------------------------------------------------------------
__global__ void score_kernel(const float* __restrict__ v) {
    __shared__ float4 a_s[32 * 33];     // 16.9 KB, row pitch 33 float4
    __shared__ float4 b_s[32 * 33];
    __shared__ float4 v_s[32];
    __shared__ float  cred[16][32];     // 2 KB column-sum reduction
    const int bi = blockIdx.z;
    const int i0 = blockIdx.x * 32, j0 = blockIdx.y * 32;
    const int tid = threadIdx.x;

    const float4* ga4 = (const float4*)g_a;
    const float4* gb4 = (const float4*)g_bm;
    for (int k = tid; k < 32 * 32; k += 256) {
        int r = k >> 5, q = k & 31;
        a_s[r * 33 + q] = ga4[(bi * NL + i0 + r) * 32 + q];
        b_s[r * 33 + q] = gb4[(bi * NL + j0 + r) * 32 + q];
    }
    if (tid < 32) v_s[tid] = ((const float4*)v)[tid];
    __syncthreads();

    const int ty = tid >> 4, tx = tid & 15;
    float acc00 = 0.f, acc01 = 0.f, acc10 = 0.f, acc11 = 0.f;
#pragma unroll 8
    for (int q = 0; q < 32; q++) {
        float4 vq = v_s[q];
        float4 a0 = a_s[ ty       * 33 + q];
        float4 a1 = a_s[(ty + 16) * 33 + q];
        float4 b0 = b_s[ tx       * 33 + q];
        float4 b1 = b_s[(tx + 16) * 33 + q];
        acc00 += vq.x * tanh_fast(a0.x + b0.x);
        acc00 += vq.y * tanh_fast(a0.y + b0.y);
        acc00 += vq.z * tanh_fast(a0.z + b0.z);
        acc00 += vq.w * tanh_fast(a0.w + b0.w);
        acc01 += vq.x * tanh_fast(a0.x + b1.x);
        acc01 += vq.y * tanh_fast(a0.y + b1.y);
        acc01 += vq.z * tanh_fast(a0.z + b1.z);
        acc01 += vq.w * tanh_fast(a0.w + b1.w);
        acc10 += vq.x * tanh_fast(a1.x + b0.x);
        acc10 += vq.y * tanh_fast(a1.y + b0.y);
        acc10 += vq.z * tanh_fast(a1.z + b0.z);
        acc10 += vq.w * tanh_fast(a1.w + b0.w);
        acc11 += vq.x * tanh_fast(a1.x + b1.x);
        acc11 += vq.y * tanh_fast(a1.y + b1.y);
        acc11 += vq.z * tanh_fast(a1.z + b1.z);
        acc11 += vq.w * tanh_fast(a1.w + b1.w);
    }
    float e00 = ex2_fast(acc00 * L2E);
    float e01 = ex2_fast(acc01 * L2E);
    float e10 = ex2_fast(acc10 * L2E);
    float e11 = ex2_fast(acc11 * L2E);

    float* sp = g_sc + (size_t)bi * NL * NL;
    sp[(i0 + ty     ) * NL + j0 + tx     ] = e00;
    sp[(i0 + ty     ) * NL + j0 + tx + 16] = e01;
    sp[(i0 + ty + 16) * NL + j0 + tx     ] = e10;
    sp[(i0 + ty + 16) * NL + j0 + tx + 16] = e11;

    // partial column sums over this block's 32 i-rows (fixed order -> determ.)
    cred[ty][tx]      = e00 + e10;
    cred[ty][tx + 16] = e01 + e11;
    __syncthreads();
    if (tid < 32) {
        float s = 0.f;
#pragma unroll
        for (int r2 = 0; r2 < 16; r2++) s += cred[r2][tid];
        g_ps[(bi * 16 + blockIdx.x) * NL + j0 + tid] = s;
    }
}

// ---------------------------------------------------------------------------
// Kernel C v9: out[b,i,d] = sum_j (E[b,i,j] * inv[b,j]) * hs[b,j,d]
// 64-j chunks (8 chunks). Preamble folds the 16 per-tile partial sums,
// rcp -> inv_sh; w staging multiplies by inv_sh.
// 128-thread CTAs, 32 i x 32 d, grid (16,4,4)=256. smem 35.4 KB.
// ---------------------------------------------------------------------------
__global__ void __launch_bounds__(128, 4)
out_kernel(const float* __restrict__ hs, float* __restrict__ out) {
    __shared__ float inv_sh[NL];                      // 2 KB
    __shared__ float w_s[2][64 * 34];                 // 17.4 KB [j][row] pitch 34
    __shared__ __align__(16) float h_s[2][64 * 32];   // 16 KB   [j][d]
    const int i0 = blockIdx.x * 32;
    const int bi = blockIdx.y;
    const int d0 = blockIdx.z * 32;
    const int tid  = threadIdx.x;
    const int wid  = tid >> 5;        // 0..3
    const int lane = tid & 31;
    const int r = lane >> 1;          // row-pair index 0..15
    const int c = lane & 1;           // float4 column 0..1
    const int dfrag = wid * 8 + c * 4;

    const float* scb = g_sc + (size_t)bi * NL * NL;

    // ---- preamble: column sums -> inverses ----
    for (int j = tid; j < NL; j += 128) {
        float s = 0.f;
#pragma unroll
        for (int it = 0; it < 16; it++)
            s += g_ps[(bi * 16 + it) * NL + j];
        inv_sh[j] = rcp_fast(s);
    }

    // ---- prologue: chunk 0 (j 0..63) ----
    float rw[16];
#pragma unroll
    for (int s = 0; s < 16; s++) {
        int k = tid + 128 * s;                 // k = row*64 + jl (coalesced jl)
        rw[s] = scb[(i0 + (k >> 6)) * NL + (k & 63)];
    }
#pragma unroll
    for (int s = 0; s < 4; s++) {
        int k = tid + 128 * s;                 // k = j*8 + seg
        int j = k >> 3, seg = k & 7;
        cp_async16(smem_u32(&h_s[0][j * 32 + seg * 4]),
                   &hs[(bi * NL + j) * ND + d0 + seg * 4]);
    }
    asm volatile("cp.async.commit_group;\n" ::: "memory");
    __syncthreads();                           // inv_sh visible
#pragma unroll
    for (int s = 0; s < 16; s++) {
        int k = tid + 128 * s;
        int row = k >> 6, jl = k & 63;
        w_s[0][jl * 34 + row] = rw[s] * inv_sh[jl];
    }
    asm volatile("cp.async.wait_group 0;\n" ::: "memory");
    __syncthreads();

    float4 acc0 = make_float4(0.f, 0.f, 0.f, 0.f);
    float4 acc1 = make_float4(0.f, 0.f, 0.f, 0.f);

    int p = 0;
    for (int ch = 0; ch < 8; ch++) {
        const int jn = (ch + 1) * 64;
        if (ch < 7) {
            // prefetch next w tile (regs) + next h tile (cp.async, other buffer)
#pragma unroll
            for (int s = 0; s < 16; s++) {
                int k = tid + 128 * s;
                rw[s] = scb[(i0 + (k >> 6)) * NL + jn + (k & 63)];
            }
#pragma unroll
            for (int s = 0; s < 4; s++) {
                int k = tid + 128 * s;
                int j = k >> 3, seg = k & 7;
                cp_async16(smem_u32(&h_s[p ^ 1][j * 32 + seg * 4]),
                           &hs[(bi * NL + jn + j) * ND + d0 + seg * 4]);
            }
            asm volatile("cp.async.commit_group;\n" ::: "memory");
        }

        const float* wp = w_s[p];
        const float* hp = h_s[p];
#pragma unroll 8
        for (int j = 0; j < 64; j++) {
            float2 wf = *(const float2*)&wp[j * 34 + r * 2];   // 128B/warp
            float4 hf = *(const float4*)&hp[j * 32 + dfrag];   // 32B/warp
            acc0.x += wf.x * hf.x;  acc0.y += wf.x * hf.y;
            acc0.z += wf.x * hf.z;  acc0.w += wf.x * hf.w;
            acc1.x += wf.y * hf.x;  acc1.y += wf.y * hf.y;
            acc1.z += wf.y * hf.z;  acc1.w += wf.y * hf.w;
        }

        if (ch < 7) {
#pragma unroll
            for (int s = 0; s < 16; s++) {
                int k = tid + 128 * s;
                int row = k >> 6, jl = k & 63;
                w_s[p ^ 1][jl * 34 + row] = rw[s] * inv_sh[jn + jl];
            }
            asm volatile("cp.async.wait_group 0;\n" ::: "memory");
            __syncthreads();
        }
        p ^= 1;
    }

    float* ob = out + ((size_t)bi * NL + i0 + r * 2) * ND + d0 + dfrag;
    *(float4*)&ob[0]  = acc0;
    *(float4*)&ob[ND] = acc1;
}

// ---------------------------------------------------------------------------
extern "C" void kernel_launch(void* const* d_in, const int* in_sizes, int n_in,
                              void* d_out, int out_size) {
    const float* hs = (const float*)d_in[0];   // (4,512,128)
    const float* W  = (const float*)d_in[1];   // (128,256)
    const float* v  = (const float*)d_in[2];   // (128,)
    float* out = (float*)d_out;                // (4,512,128)

    proj_kernel <<<dim3(64, 8),     128>>>(hs, W);
    score_kernel<<<dim3(16, 16, 4), 256>>>(v);
    out_kernel  <<<dim3(16, 4, 4),  128>>>(hs, out);
}